// round 6
// baseline (speedup 1.0000x reference)
#include <cuda_runtime.h>
#include <cuda_bf16.h>

// PatchShuffle: T=1024 (16 rows x 64 cols), B=64, C=768, STRIPE_W=48.
// perm per batch is closed-form (stable argsort of col + 64*in_stripe):
//   j < 16  -> (j < s ? j : j + 48)      [non-stripe cols ascending]
//   j >= 16 -> s + (j - 16)              [stripe cols ascending]
// inverse:
//   col < s         -> col
//   s <= col < s+48 -> 16 + col - s
//   col >= s+48     -> col - 48
//
// d_out (float32) = [ visible (256*64*768) | fwd (1024*64) | bwd (1024*64) | stripe_bounds (2*64) ]
//
// Single fused kernel: blocks [0, IDX_BLOCKS) write the index outputs (tiny,
// finishes inside wave 1), blocks [IDX_BLOCKS, ...) do the streaming gather.

#define T_DIM   1024
#define B_DIM   64
#define C_DIM   768
#define C4      192          // C_DIM / 4
#define STRIPE  48
#define KEEP    16           // NUM_COLS - STRIPE_W
#define VIS_T   256          // NUM_ROWS * KEEP
#define VIS_ELEMS (VIS_T * B_DIM * C_DIM)        // 12,582,912 floats
#define FWD_ELEMS (T_DIM * B_DIM)                // 65,536
#define IDX_ELEMS (2 * FWD_ELEMS + 2 * B_DIM)    // 131,200
#define GATHER_THREADS4 (VIS_T * B_DIM * C4)     // 3,145,728 float4s
#define GATHER_BLOCKS   (GATHER_THREADS4 / 256)  // 12,288
#define IDX_BLOCKS      ((IDX_ELEMS + 255) / 256) // 513

__device__ __forceinline__ int perm_col(int j, int s) {
    return (j < KEEP) ? (j < s ? j : j + STRIPE) : (s + j - KEEP);
}

__global__ void __launch_bounds__(256) ps_fused_kernel(
    const float4* __restrict__ in,          // patches as float4
    const int*    __restrict__ start_cols,
    float4*       __restrict__ out4,        // d_out as float4
    float*        __restrict__ out,         // d_out as float
    long long     out_size)
{
    if (blockIdx.x >= IDX_BLOCKS) {
        // ---- streaming gather of the visible region: one thread = one float4 ----
        int idx = (blockIdx.x - IDX_BLOCKS) * 256 + threadIdx.x;  // exact, no guard
        int c4  = idx % C4;
        int tb  = idx / C4;
        int b   = tb & 63;
        int t   = tb >> 6;
        int row = t >> 6;
        int j   = t & 63;
        int s   = __ldg(&start_cols[b]);
        int col = perm_col(j, s);
        int src = (row << 6) + col;                 // fwd[t][b]
        out4[idx] = in[((src << 6) + b) * C4 + c4];
        return;
    }

    // ---- index outputs: fwd, bwd, stripe_bounds (closed-form, as floats) ----
    int idx = blockIdx.x * 256 + threadIdx.x;
    if (idx >= IDX_ELEMS) return;
    long long pos = (long long)VIS_ELEMS + idx;
    if (pos >= out_size) return;

    int val;
    if (idx < FWD_ELEMS) {
        // fwd[t][b] = row*64 + perm(j)
        int t = idx >> 6, b = idx & 63;
        int row = t >> 6, j = t & 63;
        int s = __ldg(&start_cols[b]);
        val = (row << 6) + perm_col(j, s);
    } else if (idx < 2 * FWD_ELEMS) {
        // bwd[i][b] = row*64 + invperm(col)
        int i2 = idx - FWD_ELEMS;
        int i = i2 >> 6, b = i2 & 63;
        int row = i >> 6, col = i & 63;
        int s = __ldg(&start_cols[b]);
        int j = (col < s) ? col
              : (col < s + STRIPE) ? (KEEP + col - s)
              : (col - STRIPE);
        val = (row << 6) + j;
    } else {
        // stripe_bounds[r][b] = s + r*STRIPE
        int i2 = idx - 2 * FWD_ELEMS;
        int r = i2 >> 6, b = i2 & 63;
        int s = __ldg(&start_cols[b]);
        val = s + r * STRIPE;
    }
    out[pos] = (float)val;
}

extern "C" void kernel_launch(void* const* d_in, const int* in_sizes, int n_in,
                              void* d_out, int out_size)
{
    const float* patches    = (const float*)d_in[0];
    const int*   start_cols = (const int*)d_in[1];

    int grid = IDX_BLOCKS;
    if ((long long)out_size >= (long long)VIS_ELEMS) grid += GATHER_BLOCKS;

    ps_fused_kernel<<<grid, 256>>>(
        (const float4*)patches, start_cols,
        (float4*)d_out, (float*)d_out, (long long)out_size);
}

// round 8
// speedup vs baseline: 1.1389x; 1.1389x over previous
#include <cuda_runtime.h>
#include <cuda_bf16.h>

// PatchShuffle: T=1024 (16 rows x 64 cols), B=64, C=768, STRIPE_W=48.
// perm per batch is closed-form (stable argsort of col + 64*in_stripe):
//   j < 16  -> (j < s ? j : j + 48)      [non-stripe cols ascending]
//   j >= 16 -> s + (j - 16)              [stripe cols ascending]
// inverse:
//   col < s         -> col
//   s <= col < s+48 -> 16 + col - s
//   col >= s+48     -> col - 48
//
// d_out (float32) = [ visible (256*64*768) | fwd (1024*64) | bwd (1024*64) | stripe_bounds (2*64) ]
//
// Single kernel, grid identical to the fast R5 gather (12288 blocks).
// Blocks 0..512 additionally emit one index element per thread (embedded
// fusion) — hidden under the DRAM-bound gather, no extra launch.

#define T_DIM   1024
#define B_DIM   64
#define C_DIM   768
#define C4      192          // C_DIM / 4
#define STRIPE  48
#define KEEP    16           // NUM_COLS - STRIPE_W
#define VIS_T   256          // NUM_ROWS * KEEP
#define VIS_ELEMS (VIS_T * B_DIM * C_DIM)        // 12,582,912 floats
#define FWD_ELEMS (T_DIM * B_DIM)                // 65,536
#define IDX_ELEMS (2 * FWD_ELEMS + 2 * B_DIM)    // 131,200
#define GATHER_THREADS4 (VIS_T * B_DIM * C4)     // 3,145,728 float4s
#define GATHER_BLOCKS   (GATHER_THREADS4 / 256)  // 12,288
#define IDX_BLOCKS      ((IDX_ELEMS + 255) / 256) // 513

__device__ __forceinline__ int perm_col(int j, int s) {
    return (j < KEEP) ? (j < s ? j : j + STRIPE) : (s + j - KEEP);
}

__global__ void __launch_bounds__(256) ps_gather_kernel(
    const float4* __restrict__ in,          // patches as float4
    const int*    __restrict__ start_cols,
    float4*       __restrict__ out4,        // d_out as float4
    long long     out_size)
{
    // ---- streaming gather of the visible region: one thread = one float4 ----
    int idx = blockIdx.x * 256 + threadIdx.x;     // exact grid: no guard needed
    int c4  = idx % C4;
    int tb  = idx / C4;
    int b   = tb & 63;
    int t   = tb >> 6;
    int row = t >> 6;
    int j   = t & 63;
    int s   = __ldg(&start_cols[b]);
    int col = perm_col(j, s);
    int src = (row << 6) + col;                   // fwd[t][b]
    out4[idx] = in[((src << 6) + b) * C4 + c4];

    // ---- embedded index outputs in the first IDX_BLOCKS blocks ----
    if (blockIdx.x < IDX_BLOCKS) {
        int k = blockIdx.x * 256 + threadIdx.x;   // == idx, kept explicit
        if (k >= IDX_ELEMS) return;
        long long pos = (long long)VIS_ELEMS + k;
        if (pos >= out_size) return;

        int val;
        if (k < FWD_ELEMS) {
            // fwd[t][b] = row*64 + perm(j)
            int tt = k >> 6, bb = k & 63;
            int rr = tt >> 6, jj = tt & 63;
            int ss = __ldg(&start_cols[bb]);
            val = (rr << 6) + perm_col(jj, ss);
        } else if (k < 2 * FWD_ELEMS) {
            // bwd[i][b] = row*64 + invperm(col)
            int i2 = k - FWD_ELEMS;
            int ii = i2 >> 6, bb = i2 & 63;
            int rr = ii >> 6, cc = ii & 63;
            int ss = __ldg(&start_cols[bb]);
            int jj = (cc < ss) ? cc
                   : (cc < ss + STRIPE) ? (KEEP + cc - ss)
                   : (cc - STRIPE);
            val = (rr << 6) + jj;
        } else {
            // stripe_bounds[r][b] = s + r*STRIPE
            int i2 = k - 2 * FWD_ELEMS;
            int rr = i2 >> 6, bb = i2 & 63;
            int ss = __ldg(&start_cols[bb]);
            val = ss + rr * STRIPE;
        }
        ((float*)out4)[pos] = (float)val;
    }
}

// Fallback for the (unexpected) case out_size < VIS_ELEMS: index-only writes.
__global__ void __launch_bounds__(256) ps_index_only_kernel(
    const int* __restrict__ start_cols,
    float*     __restrict__ out,
    long long  out_size)
{
    int k = blockIdx.x * 256 + threadIdx.x;
    if (k >= IDX_ELEMS) return;
    long long pos = (long long)VIS_ELEMS + k;
    if (pos >= out_size) return;
    int val;
    if (k < FWD_ELEMS) {
        int tt = k >> 6, bb = k & 63;
        int rr = tt >> 6, jj = tt & 63;
        int ss = __ldg(&start_cols[bb]);
        val = (rr << 6) + perm_col(jj, ss);
    } else if (k < 2 * FWD_ELEMS) {
        int i2 = k - FWD_ELEMS;
        int ii = i2 >> 6, bb = i2 & 63;
        int rr = ii >> 6, cc = ii & 63;
        int ss = __ldg(&start_cols[bb]);
        int jj = (cc < ss) ? cc
               : (cc < ss + STRIPE) ? (KEEP + cc - ss)
               : (cc - STRIPE);
        val = (rr << 6) + jj;
    } else {
        int i2 = k - 2 * FWD_ELEMS;
        int rr = i2 >> 6, bb = i2 & 63;
        int ss = __ldg(&start_cols[bb]);
        val = ss + rr * STRIPE;
    }
    out[pos] = (float)val;
}

extern "C" void kernel_launch(void* const* d_in, const int* in_sizes, int n_in,
                              void* d_out, int out_size)
{
    const float* patches    = (const float*)d_in[0];
    const int*   start_cols = (const int*)d_in[1];

    if ((long long)out_size >= (long long)VIS_ELEMS) {
        ps_gather_kernel<<<GATHER_BLOCKS, 256>>>(
            (const float4*)patches, start_cols,
            (float4*)d_out, (long long)out_size);
    } else {
        ps_index_only_kernel<<<IDX_BLOCKS, 256>>>(
            start_cols, (float*)d_out, (long long)out_size);
    }
}

// round 9
// speedup vs baseline: 1.3928x; 1.2229x over previous
#include <cuda_runtime.h>
#include <cuda_bf16.h>

// PatchShuffle: T=1024 (16 rows x 64 cols), B=64, C=768, STRIPE_W=48.
// perm per batch is closed-form (stable argsort of col + 64*in_stripe):
//   j < 16  -> (j < s ? j : j + 48)      [non-stripe cols ascending]
//   j >= 16 -> s + (j - 16)              [stripe cols ascending]
// inverse:
//   col < s         -> col
//   s <= col < s+48 -> 16 + col - s
//   col >= s+48     -> col - 48
//
// d_out (float32) = [ visible (256*64*768) | fwd (1024*64) | bwd (1024*64) | stripe_bounds (2*64) ]
//
// Single kernel. Each thread gathers FOUR independent float4s (front-batched
// LDG.128s -> MLP_p1=4 for latency hiding; kernel was latency-bound at MLP=1:
// DRAM 46%, issue 28%, nothing saturated). Index outputs are emitted as
// float4 stores by the first ~129 blocks (tiny, hidden under the gather).

#define T_DIM   1024
#define B_DIM   64
#define C_DIM   768
#define C4      192          // C_DIM / 4
#define STRIPE  48
#define KEEP    16           // NUM_COLS - STRIPE_W
#define VIS_T   256          // NUM_ROWS * KEEP
#define VIS_ELEMS (VIS_T * B_DIM * C_DIM)        // 12,582,912 floats
#define VIS_F4    (VIS_ELEMS / 4)                // 3,145,728 float4s
#define FWD_ELEMS (T_DIM * B_DIM)                // 65,536
#define IDX_ELEMS (2 * FWD_ELEMS + 2 * B_DIM)    // 131,200
#define IDX_F4    (IDX_ELEMS / 4)                // 32,800 float4s
#define EPT       4                              // float4s per thread
#define BLOCK     256
#define F4_PER_BLOCK (BLOCK * EPT)               // 1024
#define GATHER_BLOCKS (VIS_F4 / F4_PER_BLOCK)    // 3072
#define IDX_BLOCKS ((IDX_F4 + BLOCK - 1) / BLOCK) // 129

__device__ __forceinline__ int perm_col(int j, int s) {
    return (j < KEEP) ? (j < s ? j : j + STRIPE) : (s + j - KEEP);
}

__device__ __forceinline__ int idx_val(int k, const int* __restrict__ start_cols) {
    // k in [0, IDX_ELEMS): fwd | bwd | stripe_bounds, all closed-form
    if (k < FWD_ELEMS) {
        int t = k >> 6, b = k & 63;
        int row = t >> 6, j = t & 63;
        int s = __ldg(&start_cols[b]);
        return (row << 6) + perm_col(j, s);
    } else if (k < 2 * FWD_ELEMS) {
        int i2 = k - FWD_ELEMS;
        int i = i2 >> 6, b = i2 & 63;
        int row = i >> 6, col = i & 63;
        int s = __ldg(&start_cols[b]);
        int j = (col < s) ? col
              : (col < s + STRIPE) ? (KEEP + col - s)
              : (col - STRIPE);
        return (row << 6) + j;
    } else {
        int i2 = k - 2 * FWD_ELEMS;
        int r = i2 >> 6, b = i2 & 63;
        int s = __ldg(&start_cols[b]);
        return s + r * STRIPE;
    }
}

__device__ __forceinline__ const float4* src_ptr(
    const float4* __restrict__ in, const int* __restrict__ start_cols, int idx)
{
    int c4  = idx % C4;
    int tb  = idx / C4;
    int b   = tb & 63;
    int t   = tb >> 6;
    int row = t >> 6;
    int j   = t & 63;
    int s   = __ldg(&start_cols[b]);
    int col = perm_col(j, s);
    int src = (row << 6) + col;                   // fwd[t][b]
    return &in[((src << 6) + b) * C4 + c4];
}

__global__ void __launch_bounds__(BLOCK) ps_gather_kernel(
    const float4* __restrict__ in,          // patches as float4
    const int*    __restrict__ start_cols,
    float4*       __restrict__ out4,        // d_out as float4
    long long     out_size)
{
    // ---- streaming gather: 4 independent float4s per thread ----
    int base = blockIdx.x * F4_PER_BLOCK + threadIdx.x;

    const float4* p0 = src_ptr(in, start_cols, base);
    const float4* p1 = src_ptr(in, start_cols, base + BLOCK);
    const float4* p2 = src_ptr(in, start_cols, base + 2 * BLOCK);
    const float4* p3 = src_ptr(in, start_cols, base + 3 * BLOCK);

    float4 v0 = *p0;
    float4 v1 = *p1;
    float4 v2 = *p2;
    float4 v3 = *p3;

    out4[base]             = v0;
    out4[base + BLOCK]     = v1;
    out4[base + 2 * BLOCK] = v2;
    out4[base + 3 * BLOCK] = v3;

    // ---- embedded index outputs: one float4 per thread in first blocks ----
    int t4 = blockIdx.x * BLOCK + threadIdx.x;
    if (t4 < IDX_F4) {
        int k = t4 * 4;
        long long pos = (long long)VIS_ELEMS + k;
        if (pos + 3 < out_size) {
            float4 v;
            v.x = (float)idx_val(k,     start_cols);
            v.y = (float)idx_val(k + 1, start_cols);
            v.z = (float)idx_val(k + 2, start_cols);
            v.w = (float)idx_val(k + 3, start_cols);
            out4[VIS_F4 + t4] = v;
        }
    }
}

// Fallback if out_size < full layout (unexpected): index-only scalar writes.
__global__ void __launch_bounds__(BLOCK) ps_index_only_kernel(
    const int* __restrict__ start_cols,
    float*     __restrict__ out,
    long long  out_size)
{
    int k = blockIdx.x * BLOCK + threadIdx.x;
    if (k >= IDX_ELEMS) return;
    long long pos = (long long)VIS_ELEMS + k;
    if (pos >= out_size) return;
    out[pos] = (float)idx_val(k, start_cols);
}

extern "C" void kernel_launch(void* const* d_in, const int* in_sizes, int n_in,
                              void* d_out, int out_size)
{
    const float* patches    = (const float*)d_in[0];
    const int*   start_cols = (const int*)d_in[1];

    if ((long long)out_size >= (long long)(VIS_ELEMS + IDX_ELEMS)) {
        ps_gather_kernel<<<GATHER_BLOCKS, BLOCK>>>(
            (const float4*)patches, start_cols,
            (float4*)d_out, (long long)out_size);
    } else {
        ps_index_only_kernel<<<(IDX_ELEMS + BLOCK - 1) / BLOCK, BLOCK>>>(
            start_cols, (float*)d_out, (long long)out_size);
    }
}